// round 10
// baseline (speedup 1.0000x reference)
#include <cuda_runtime.h>
#include <cstdint>

// Problem constants (match reference)
#define U_DIM 2000
#define I_DIM 2000
#define K_DIM 32
#define B_DIM 16384
#define NEIGHBORHOOD 32.0f

#define THREADS 128
#define WARPS_PER_BLOCK (THREADS / 32)      // 4
#define SPW 8                               // samples per warp
#define SAMPLES_PER_BLOCK (WARPS_PER_BLOCK * SPW)   // 32

// R5 winning shape (10.46us) minus the smem b_item staging:
// R1 vs R2 showed the b_item gather is free when L1-resident (8KB array),
// so drop the smem fill (63 wf/block), the barrier, and the smem footprint.
// All loads plain __ldg (both .cs and .cg policies regressed in R6/R7).
__global__ void __launch_bounds__(THREADS) item_reg_kernel(
    const float* __restrict__ rating_matrix,  // [U, I]
    const int*   __restrict__ qtus,           // [U, I, K]
    const float* __restrict__ weight,         // [I, I]
    const float* __restrict__ b_user,         // [U]
    const float* __restrict__ b_item,         // [I]
    const int*   __restrict__ users,          // [B]
    const int*   __restrict__ items,          // [B]
    float*       __restrict__ out)            // [B]
{
    const int warp_in_block = threadIdx.x >> 5;
    const int lane          = threadIdx.x & 31;
    const int b0 = (blockIdx.x * WARPS_PER_BLOCK + warp_in_block) * SPW;

    // ---- sample indices: two 16B vector loads each ----
    const int4 uv0 = *(const int4*)(users + b0);
    const int4 uv1 = *(const int4*)(users + b0 + 4);
    const int4 tv0 = *(const int4*)(items + b0);
    const int4 tv1 = *(const int4*)(items + b0 + 4);
    const int u[SPW] = { uv0.x, uv0.y, uv0.z, uv0.w, uv1.x, uv1.y, uv1.z, uv1.w };
    const int t[SPW] = { tv0.x, tv0.y, tv0.z, tv0.w, tv1.x, tv1.y, tv1.z, tv1.w };

    // ---- batch: 8 independent coalesced qtus row loads ----
    int j[SPW];
    #pragma unroll
    for (int s = 0; s < SPW; s++) {
        const unsigned ut = (unsigned)u[s] * I_DIM + (unsigned)t[s];
        j[s] = __ldg(&qtus[ut * K_DIM + lane]);   // 128B coalesced line
    }

    // ---- batch: 24 independent scattered gathers in flight ----
    // weight first (irreducible 32 lines/sample), then rating, then b_item
    // (L1-resident 8KB -> near-free replays).
    float w[SPW], r[SPW], bj[SPW];
    #pragma unroll
    for (int s = 0; s < SPW; s++)
        w[s] = __ldg(&weight[(unsigned)j[s] * I_DIM + (unsigned)t[s]]);
    #pragma unroll
    for (int s = 0; s < SPW; s++)
        r[s] = __ldg(&rating_matrix[(unsigned)u[s] * I_DIM + (unsigned)j[s]]);
    #pragma unroll
    for (int s = 0; s < SPW; s++)
        bj[s] = __ldg(&b_item[j[s]]);

    // ---- uniform bias loads (broadcast, L1-hot) ----
    float bu[SPW];
    #pragma unroll
    for (int s = 0; s < SPW; s++)
        bu[s] = __ldg(&b_user[u[s]]);

    // ---- compute + interleaved warp reductions ----
    float v[SPW];
    #pragma unroll
    for (int s = 0; s < SPW; s++)
        v[s] = w[s] * (r[s] - bu[s] - bj[s]);

    #pragma unroll
    for (int off = 16; off > 0; off >>= 1) {
        #pragma unroll
        for (int s = 0; s < SPW; s++)
            v[s] += __shfl_down_sync(0xFFFFFFFFu, v[s], off);
    }

    if (lane == 0) {
        #pragma unroll
        for (int s = 0; s < SPW; s++)
            out[b0 + s] = bu[s] + __ldg(&b_item[t[s]]) + v[s] * (1.0f / NEIGHBORHOOD);
    }
}

extern "C" void kernel_launch(void* const* d_in, const int* in_sizes, int n_in,
                              void* d_out, int out_size)
{
    const float* rating_matrix = (const float*)d_in[0];
    const int*   qtus          = (const int*)  d_in[1];
    const float* weight        = (const float*)d_in[2];
    const float* b_user        = (const float*)d_in[3];
    const float* b_item        = (const float*)d_in[4];
    const int*   users         = (const int*)  d_in[5];
    const int*   items         = (const int*)  d_in[6];
    float* out = (float*)d_out;

    const int blocks = B_DIM / SAMPLES_PER_BLOCK;  // 512
    item_reg_kernel<<<blocks, THREADS>>>(rating_matrix, qtus, weight, b_user,
                                         b_item, users, items, out);
}

// round 12
// speedup vs baseline: 1.0239x; 1.0239x over previous
#include <cuda_runtime.h>
#include <cstdint>

// Problem constants (match reference)
#define U_DIM 2000
#define I_DIM 2000
#define K_DIM 32
#define B_DIM 16384
#define NEIGHBORHOOD 32.0f

#define THREADS 128
#define WARPS_PER_BLOCK (THREADS / 32)      // 4
#define SPW 16                              // samples per warp
#define SAMPLES_PER_BLOCK (WARPS_PER_BLOCK * SPW)   // 64

// R5 recipe (best: 10.46us = smem b_item + plain __ldg + 128-thr blocks),
// ILP doubled to SPW=16: 16 coalesced qtus rows then 32 scattered gathers
// in flight per warp (~48 LDGs, near the ~55/warp outstanding ceiling).
// smem fill now amortized over 64 samples/block.
__global__ void __launch_bounds__(THREADS) item_reg_kernel(
    const float* __restrict__ rating_matrix,  // [U, I]
    const int*   __restrict__ qtus,           // [U, I, K]
    const float* __restrict__ weight,         // [I, I]
    const float* __restrict__ b_user,         // [U]
    const float* __restrict__ b_item,         // [I]
    const int*   __restrict__ users,          // [B]
    const int*   __restrict__ items,          // [B]
    float*       __restrict__ out)            // [B]
{
    __shared__ float s_bitem[I_DIM];

    // Cooperative coalesced fill of b_item into smem (2000 floats = 8KB).
    #pragma unroll
    for (int i = threadIdx.x; i < I_DIM; i += THREADS)
        s_bitem[i] = __ldg(&b_item[i]);

    const int warp_in_block = threadIdx.x >> 5;
    const int lane          = threadIdx.x & 31;
    const int b0 = (blockIdx.x * WARPS_PER_BLOCK + warp_in_block) * SPW;

    // ---- sample indices: four 16B vector loads each ----
    int u[SPW], t[SPW];
    #pragma unroll
    for (int q = 0; q < SPW / 4; q++) {
        const int4 uv = *(const int4*)(users + b0 + 4 * q);
        const int4 tv = *(const int4*)(items + b0 + 4 * q);
        u[4*q+0] = uv.x; u[4*q+1] = uv.y; u[4*q+2] = uv.z; u[4*q+3] = uv.w;
        t[4*q+0] = tv.x; t[4*q+1] = tv.y; t[4*q+2] = tv.z; t[4*q+3] = tv.w;
    }

    // ---- batch: 16 independent coalesced qtus row loads ----
    int j[SPW];
    #pragma unroll
    for (int s = 0; s < SPW; s++) {
        const unsigned ut = (unsigned)u[s] * I_DIM + (unsigned)t[s];
        j[s] = __ldg(&qtus[ut * K_DIM + lane]);   // 128B coalesced line
    }

    __syncthreads();   // smem b_item ready

    // ---- batch: 32 independent scattered gathers in flight ----
    float w[SPW], r[SPW];
    #pragma unroll
    for (int s = 0; s < SPW; s++)
        w[s] = __ldg(&weight[(unsigned)j[s] * I_DIM + (unsigned)t[s]]);
    #pragma unroll
    for (int s = 0; s < SPW; s++)
        r[s] = __ldg(&rating_matrix[(unsigned)u[s] * I_DIM + (unsigned)j[s]]);

    // ---- uniform bias loads (broadcast, L1-hot) ----
    float bu[SPW];
    #pragma unroll
    for (int s = 0; s < SPW; s++)
        bu[s] = __ldg(&b_user[u[s]]);

    // ---- compute + interleaved warp reductions ----
    float v[SPW];
    #pragma unroll
    for (int s = 0; s < SPW; s++)
        v[s] = w[s] * (r[s] - bu[s] - s_bitem[j[s]]);

    #pragma unroll
    for (int off = 16; off > 0; off >>= 1) {
        #pragma unroll
        for (int s = 0; s < SPW; s++)
            v[s] += __shfl_down_sync(0xFFFFFFFFu, v[s], off);
    }

    if (lane == 0) {
        #pragma unroll
        for (int s = 0; s < SPW; s++)
            out[b0 + s] = bu[s] + s_bitem[t[s]] + v[s] * (1.0f / NEIGHBORHOOD);
    }
}

extern "C" void kernel_launch(void* const* d_in, const int* in_sizes, int n_in,
                              void* d_out, int out_size)
{
    const float* rating_matrix = (const float*)d_in[0];
    const int*   qtus          = (const int*)  d_in[1];
    const float* weight        = (const float*)d_in[2];
    const float* b_user        = (const float*)d_in[3];
    const float* b_item        = (const float*)d_in[4];
    const int*   users         = (const int*)  d_in[5];
    const int*   items         = (const int*)  d_in[6];
    float* out = (float*)d_out;

    const int blocks = B_DIM / SAMPLES_PER_BLOCK;  // 256
    item_reg_kernel<<<blocks, THREADS>>>(rating_matrix, qtus, weight, b_user,
                                         b_item, users, items, out);
}